// round 16
// baseline (speedup 1.0000x reference)
#include <cuda_runtime.h>
#include <cuda_bf16.h>

#define BS 128
#define GS 201
#define DIM 128
#define HALF 100
#define GS2 (GS*GS)
#define OUTS (HALF + GS2)
#define NORMF 0.08838834764831845f
#define NTILES 26

// ---- device scratch ----
__device__ float g_gb[BS*DIM];
__device__ float g_h[BS*GS*DIM];
__device__ float g_hQ[BS*GS*DIM];
__device__ float g_hK[BS*GS*DIM];
__device__ float g_Mt[8*DIM*DIM];
__device__ float g_u[BS*GS*32];
__device__ float g_v[BS*GS*32];
__device__ float g_part[BS*NTILES];
__device__ float g_sums[BS];

// ---- f32x2 helpers ----
__device__ __forceinline__ unsigned long long pack2(float lo, float hi){
    unsigned long long r; asm("mov.b64 %0, {%1, %2};" : "=l"(r) : "f"(lo), "f"(hi)); return r;
}
__device__ __forceinline__ float2 unpack2(unsigned long long v){
    float2 r; asm("mov.b64 {%0, %1}, %2;" : "=f"(r.x), "=f"(r.y) : "l"(v)); return r;
}
__device__ __forceinline__ unsigned long long fma2(unsigned long long a, unsigned long long b, unsigned long long c){
    unsigned long long r; asm("fma.rn.f32x2 %0, %1, %2, %3;" : "=l"(r) : "l"(a), "l"(b), "l"(c)); return r;
}
__device__ __forceinline__ float fast_tanh(float y){
    y = fminf(fmaxf(y, -15.f), 15.f);
    float e = __expf(2.f*y);
    return __fdividef(e-1.f, e+1.f);
}

// ---- k_pg: fused k_prep (blocks 0..63) + k_gg (blocks 64..191) ----
__global__ __launch_bounds__(256) void k_pg(const float* __restrict__ Wq1, const float* __restrict__ Wk1,
                                            const float* __restrict__ Wq2, const float* __restrict__ Wk2,
                                            const float* __restrict__ h_em, const float* __restrict__ Wg){
    int blk = blockIdx.x;
    int tid = threadIdx.x;
    if (blk < 64){
        __shared__ float Wqs[16][33];
        __shared__ float Wks[32][129];
        int mat = blk >> 3, kt = blk & 7;
        int s = mat >> 2, h = mat & 3;
        const float* Wq = (s ? Wq2 : Wq1) + h*DIM*DIM;
        const float* Wk = (s ? Wk2 : Wk1) + h*DIM*DIM;
        int j = tid & 127, rr = tid >> 7;
        float acc[8];
        #pragma unroll
        for (int r = 0; r < 8; ++r) acc[r] = 0.f;
        for (int e0 = 0; e0 < DIM; e0 += 32){
            for (int idx = tid; idx < 16*32; idx += 256){
                int r = idx >> 5, e = idx & 31;
                Wqs[r][e] = Wq[(kt*16 + r)*DIM + e0 + e];
            }
            for (int idx = tid; idx < 128*32; idx += 256){
                int row = idx >> 5, e = idx & 31;
                Wks[e][row] = Wk[row*DIM + e0 + e];
            }
            __syncthreads();
            #pragma unroll 8
            for (int e = 0; e < 32; ++e){
                float wv = Wks[e][j];
                #pragma unroll
                for (int r = 0; r < 8; ++r)
                    acc[r] = fmaf(Wqs[rr*8 + r][e], wv, acc[r]);
            }
            __syncthreads();
        }
        #pragma unroll
        for (int r = 0; r < 8; ++r)
            g_Mt[mat*DIM*DIM + (kt*16 + rr*8 + r)*DIM + j] = acc[r];
    } else {
        __shared__ float xs[DIM];
        int b = blk - 64, d = tid;
        if (d < DIM){
            const float* p = h_em + (size_t)b*GS*DIM + d;
            float m = -1e30f;
            for (int g = 0; g < GS; ++g) m = fmaxf(m, p[(size_t)g*DIM]);
            xs[d] = m;
        }
        __syncthreads();
        if (d < DIM){
            float acc = 0.f;
            #pragma unroll 8
            for (int i = 0; i < DIM; ++i) acc = fmaf(xs[i], Wg[i*DIM+d], acc);
            g_gb[b*DIM+d] = acc;
        }
    }
}

// ---- GEMM mode 0 (R12 original): h = h_em@Wn + gb ----
__global__ __launch_bounds__(256) void k_gemm0(const float* __restrict__ A, const float* __restrict__ B){
    __shared__ float As[64][17];
    __shared__ float Bs[16][128];
    int tid = threadIdx.x;
    int tx = tid & 15, ty = tid >> 4;
    int row0 = blockIdx.x * 64;
    float acc[4][8];
    #pragma unroll
    for (int a = 0; a < 4; ++a)
        #pragma unroll
        for (int c = 0; c < 8; ++c) acc[a][c] = 0.f;
    int la_r = tid >> 2, la_k = (tid & 3)*4;
    int lb_r = tid >> 4, lb_c = (tid & 15)*8;
    for (int kc = 0; kc < DIM; kc += 16){
        float4 av = *reinterpret_cast<const float4*>(A + (size_t)(row0+la_r)*DIM + kc + la_k);
        const float* bp = B + (kc+lb_r)*DIM + lb_c;
        float4 bv0 = *reinterpret_cast<const float4*>(bp);
        float4 bv1 = *reinterpret_cast<const float4*>(bp+4);
        As[la_r][la_k+0]=av.x; As[la_r][la_k+1]=av.y; As[la_r][la_k+2]=av.z; As[la_r][la_k+3]=av.w;
        *reinterpret_cast<float4*>(&Bs[lb_r][lb_c])   = bv0;
        *reinterpret_cast<float4*>(&Bs[lb_r][lb_c+4]) = bv1;
        __syncthreads();
        #pragma unroll
        for (int k = 0; k < 16; ++k){
            float a0=As[ty*4+0][k], a1=As[ty*4+1][k], a2=As[ty*4+2][k], a3=As[ty*4+3][k];
            float4 b0 = *reinterpret_cast<const float4*>(&Bs[k][tx*8]);
            float4 b1 = *reinterpret_cast<const float4*>(&Bs[k][tx*8+4]);
            float bb[8] = {b0.x,b0.y,b0.z,b0.w,b1.x,b1.y,b1.z,b1.w};
            #pragma unroll
            for (int c = 0; c < 8; ++c){
                acc[0][c]=fmaf(a0,bb[c],acc[0][c]); acc[1][c]=fmaf(a1,bb[c],acc[1][c]);
                acc[2][c]=fmaf(a2,bb[c],acc[2][c]); acc[3][c]=fmaf(a3,bb[c],acc[3][c]);
            }
        }
        __syncthreads();
    }
    #pragma unroll
    for (int a = 0; a < 4; ++a){
        int row = row0 + ty*4 + a;
        #pragma unroll
        for (int c = 0; c < 8; ++c)
            g_h[(size_t)row*DIM + tx*8 + c] = acc[a][c] + g_gb[(row/GS)*DIM + tx*8 + c];
    }
}

// ---- k_uvq: fused qW (via Mt) + per-node layer-1 pre-activations. grid (BS, 4). ----
__global__ __launch_bounds__(256) void k_uvq(const int* __restrict__ rec, const int* __restrict__ fixed_action,
                                             const float* __restrict__ i_w1, const float* __restrict__ i_b1){
    __shared__ float xsel[2][DIM];
    __shared__ float qw[16*133];
    __shared__ float xg[8][DIM], xn[8][DIM];
    __shared__ float sfeat[8][16];
    __shared__ float w1s[16][32];
    __shared__ float b1s[32];
    __shared__ int recs[GS];
    int b = blockIdx.x, cq = blockIdx.y, tid = threadIdx.x;

    for (int idx = tid; idx < GS; idx += 256) recs[idx] = rec[b*GS + idx];
    for (int idx = tid; idx < 16*32; idx += 256) w1s[idx>>5][idx&31] = i_w1[idx];
    if (tid < 32) b1s[tid] = i_b1[tid];
    {
        int pos = 1 + fixed_action[b*3];
        int vs = tid >> 7, e = tid & 127;
        int row = vs ? pos + HALF : pos;
        xsel[vs][e] = g_h[((size_t)b*GS + row)*DIM + e];
    }
    __syncthreads();

    #pragma unroll
    for (int r = 0; r < 8; ++r){
        int idx = r*256 + tid;
        int vec = idx >> 7, t = idx & 127;
        int combo = vec >> 2, head = vec & 3;
        int mat = (combo & 1)*4 + head;
        const float* Mh = g_Mt + (size_t)mat*DIM*DIM;
        const float* x = xsel[(combo & 2) ? 1 : 0];
        float acc = 0.f;
        #pragma unroll 4
        for (int k = 0; k < DIM; ++k) acc = fmaf(x[k], Mh[k*DIM + t], acc);
        qw[vec*133 + t] = acc;
    }
    __syncthreads();

    int c_end = min(cq*7 + 7, 26);
    for (int c = cq*7; c < c_end; ++c){
        {
            int g_loc = tid >> 5, e4 = tid & 31;
            int g = c*8 + g_loc;
            int gc = min(g, GS-1);
            const float4* hg = reinterpret_cast<const float4*>(g_h + ((size_t)b*GS + gc)*DIM) + e4;
            const float4* hn = reinterpret_cast<const float4*>(g_h + ((size_t)b*GS + recs[gc])*DIM) + e4;
            *(reinterpret_cast<float4*>(&xg[g_loc][0]) + e4) = *hg;
            *(reinterpret_cast<float4*>(&xn[g_loc][0]) + e4) = *hn;
        }
        __syncthreads();
        {
            int dot_id = tid >> 1, half = tid & 1;
            int g_loc = dot_id >> 4, vec = dot_id & 15;
            int combo = vec >> 2;
            const float* x = (combo & 1) ? xn[g_loc] : xg[g_loc];
            const float* q = qw + vec*133;
            float p = 0.f;
            #pragma unroll 8
            for (int i2 = 0; i2 < 64; ++i2){
                int e = 2*i2 + half;
                p = fmaf(q[e], x[e], p);
            }
            p += __shfl_xor_sync(0xffffffffu, p, 1);
            if (half == 0) sfeat[g_loc][vec] = p * NORMF;
        }
        __syncthreads();
        #pragma unroll
        for (int r = 0; r < 2; ++r){
            int out = r*256 + tid;
            int g_loc = out >> 6, c32 = out & 63;
            int g = c*8 + g_loc;
            if (g < GS){
                if (c32 < 32){
                    float u = b1s[c32];
                    #pragma unroll
                    for (int f = 0; f < 8; ++f) u = fmaf(sfeat[g_loc][f], w1s[f][c32], u);
                    g_u[((size_t)b*GS + g)*32 + c32] = u;
                } else {
                    int cc = c32 - 32;
                    float v = 0.f;
                    #pragma unroll
                    for (int f = 0; f < 8; ++f) v = fmaf(sfeat[g_loc][8+f], w1s[8+f][cc], v);
                    g_v[((size_t)b*GS + g)*32 + cc] = v;
                }
            }
        }
        __syncthreads();
    }
}

// ---- GEMM QK v5: split Q/K by blockIdx.y, 64-row tile, f32x2, double-buffered pipeline ----
__global__ __launch_bounds__(256, 3) void k_gemmQK(const float* __restrict__ BQ, const float* __restrict__ BK){
    __shared__ float As[2][64][17];
    __shared__ float Bs[2][16][128];
    const float* A = g_h;
    const float* B = blockIdx.y ? BK : BQ;
    float* C = blockIdx.y ? g_hK : g_hQ;
    int tid = threadIdx.x;
    int tx = tid & 15, ty = tid >> 4;
    int row0 = blockIdx.x * 64;
    unsigned long long acc[4][4];
    #pragma unroll
    for (int a = 0; a < 4; ++a)
        #pragma unroll
        for (int c = 0; c < 4; ++c) acc[a][c] = 0ull;
    int la_r = tid >> 2, la_k = (tid & 3)*4;
    int lb_r = tid >> 4, lb_c = (tid & 15)*8;
    const float* Arow = A + (size_t)(row0+la_r)*DIM + la_k;

    // prologue: load tile 0 into buffer 0
    {
        float4 av = *reinterpret_cast<const float4*>(Arow);
        size_t boff = (size_t)(lb_c>>5)*4096 + lb_r*32 + (lb_c&31);
        float4 bv0 = *reinterpret_cast<const float4*>(B + boff);
        float4 bv1 = *reinterpret_cast<const float4*>(B + boff + 4);
        As[0][la_r][la_k+0]=av.x; As[0][la_r][la_k+1]=av.y; As[0][la_r][la_k+2]=av.z; As[0][la_r][la_k+3]=av.w;
        *reinterpret_cast<float4*>(&Bs[0][lb_r][lb_c])   = bv0;
        *reinterpret_cast<float4*>(&Bs[0][lb_r][lb_c+4]) = bv1;
    }
    __syncthreads();

    int cur = 0;
    #pragma unroll
    for (int it = 0; it < 8; ++it){
        // prefetch next tile into alternate buffer (overlaps with compute below)
        if (it < 7){
            int kc = (it + 1) * 16;
            float4 av = *reinterpret_cast<const float4*>(Arow + kc);
            size_t boff = (size_t)(lb_c>>5)*4096 + (kc+lb_r)*32 + (lb_c&31);
            float4 bv0 = *reinterpret_cast<const float4*>(B + boff);
            float4 bv1 = *reinterpret_cast<const float4*>(B + boff + 4);
            int nxt = cur ^ 1;
            As[nxt][la_r][la_k+0]=av.x; As[nxt][la_r][la_k+1]=av.y;
            As[nxt][la_r][la_k+2]=av.z; As[nxt][la_r][la_k+3]=av.w;
            *reinterpret_cast<float4*>(&Bs[nxt][lb_r][lb_c])   = bv0;
            *reinterpret_cast<float4*>(&Bs[nxt][lb_r][lb_c+4]) = bv1;
        }
        #pragma unroll
        for (int k = 0; k < 16; ++k){
            unsigned long long ad[4];
            #pragma unroll
            for (int r = 0; r < 4; ++r){
                float a = As[cur][ty*4+r][k];
                ad[r] = pack2(a, a);
            }
            const ulonglong2* bp2 = reinterpret_cast<const ulonglong2*>(&Bs[cur][k][tx*8]);
            ulonglong2 b01 = bp2[0];
            ulonglong2 b23 = bp2[1];
            #pragma unroll
            for (int r = 0; r < 4; ++r){
                acc[r][0] = fma2(ad[r], b01.x, acc[r][0]);
                acc[r][1] = fma2(ad[r], b01.y, acc[r][1]);
                acc[r][2] = fma2(ad[r], b23.x, acc[r][2]);
                acc[r][3] = fma2(ad[r], b23.y, acc[r][3]);
            }
        }
        __syncthreads();
        cur ^= 1;
    }
    #pragma unroll
    for (int a = 0; a < 4; ++a){
        int row = row0 + ty*4 + a;
        float* crow = C + (size_t)row*DIM + tx*8;
        #pragma unroll
        for (int c = 0; c < 4; ++c){
            float2 r = unpack2(acc[a][c]);
            crow[2*c]   = r.x;
            crow[2*c+1] = r.y;
        }
    }
}

// ---- removal scores ----
__global__ void k_removal(const int* __restrict__ rec, const float* __restrict__ sig,
                          const float* __restrict__ w1, const float* __restrict__ b1,
                          const float* __restrict__ w2, const float* __restrict__ b2,
                          const float* __restrict__ w3, const float* __restrict__ b3,
                          float* __restrict__ out){
    int b = blockIdx.x, t = threadIdx.x;
    __shared__ int rec_s[GS], pre_s[GS];
    __shared__ float red[4];
    __shared__ float tot_s;
    for (int g = t; g < GS; g += 128) rec_s[g] = rec[b*GS+g];
    __syncthreads();
    for (int g = t; g < GS; g += 128) pre_s[rec_s[g]] = g;
    __syncthreads();
    float e = 0.f;
    if (t < HALF){
        float feat[12];
        #pragma unroll
        for (int hf = 0; hf < 2; ++hf){
            int g = 1 + hf*HALF + t;
            int pg = pre_s[g];
            int og = rec_s[rec_s[g]];
            const float* Qg = g_hQ + ((size_t)b*GS + g )*DIM;
            const float* Kg = g_hK + ((size_t)b*GS + g )*DIM;
            const float* Qp = g_hQ + ((size_t)b*GS + pg)*DIM;
            const float* Kp = g_hK + ((size_t)b*GS + og)*DIM;
            #pragma unroll
            for (int h = 0; h < 4; ++h){
                float c1=0.f, c2=0.f, c3=0.f;
                #pragma unroll
                for (int k = 0; k < 32; ++k){
                    float qp=Qp[h*32+k], kg=Kg[h*32+k], qg=Qg[h*32+k], kp=Kp[h*32+k];
                    c1 = fmaf(qp, kg, c1);
                    c2 = fmaf(qg, kp, c2);
                    c3 = fmaf(qp, kp, c3);
                }
                feat[hf*4+h] = c1 + c2 - c3;
            }
        }
        #pragma unroll
        for (int s4 = 0; s4 < 4; ++s4) feat[8+s4] = sig[b*4*HALF + s4*HALF + t];
        float x1[32];
        #pragma unroll
        for (int c = 0; c < 32; ++c){
            float a = b1[c];
            #pragma unroll
            for (int f = 0; f < 12; ++f) a = fmaf(feat[f], w1[f*32+c], a);
            x1[c] = fmaxf(a, 0.f);
        }
        float y = b3[0];
        #pragma unroll
        for (int o = 0; o < 32; ++o){
            float a = b2[o];
            #pragma unroll
            for (int k = 0; k < 32; ++k) a = fmaf(x1[k], w2[k*32+o], a);
            y = fmaf(fmaxf(a, 0.f), w3[o], y);
        }
        e = __expf(6.f * tanhf(y));
    }
    float w = e;
    #pragma unroll
    for (int o = 16; o; o >>= 1) w += __shfl_xor_sync(0xffffffffu, w, o);
    if ((t & 31) == 0) red[t>>5] = w;
    __syncthreads();
    if (t == 0) tot_s = red[0]+red[1]+red[2]+red[3];
    __syncthreads();
    if (t < HALF) out[(size_t)b*OUTS + t] = e / tot_s;
}

// ---- table MLP v8 (unchanged, best): o-packed accs + 4-j amortization + coalesced vp ----
__global__ __launch_bounds__(256, 2) void k_table(
        const float* __restrict__ i_w2, const float* __restrict__ i_b2,
        const float* __restrict__ i_w3, const float* __restrict__ i_b3,
        const unsigned char* __restrict__ mask, float* __restrict__ out){
    __shared__ unsigned long long w2p[32][16];
    __shared__ float2 vp[32][101];
    __shared__ float us[8][32];
    __shared__ unsigned long long b2p[16];
    __shared__ float w3s[32];
    __shared__ float red[8];
    int tid = threadIdx.x, b = blockIdx.y, it = blockIdx.x;
    int lane = tid & 31, il = tid >> 5;

    const unsigned long long* w2u = reinterpret_cast<const unsigned long long*>(i_w2);
    #pragma unroll
    for (int r = 0; r < 2; ++r){
        int idx = r*256 + tid;
        w2p[idx >> 4][idx & 15] = w2u[idx];
    }
    if (tid < 16) b2p[tid] = reinterpret_cast<const unsigned long long*>(i_b2)[tid];
    if (tid < 32) w3s[tid] = i_w3[tid];
    const float* vbase = g_v + (size_t)b*GS*32;
    for (int j = il; j < GS; j += 8){
        float val = vbase[(size_t)j*32 + lane];
        reinterpret_cast<float*>(&vp[lane][j >> 1])[j & 1] = val;
    }
    if (il == 0) vp[lane][100].y = vbase[(size_t)200*32 + lane];
    {
        int i = it*8 + il;
        us[il][lane] = (i < GS) ? g_u[((size_t)b*GS + i)*32 + lane] : 0.f;
    }
    __syncthreads();

    int i = it*8 + il;
    bool iok = (i < GS);
    float b3v = i_b3[0];
    float lsum = 0.f;
    const unsigned char* mrow = mask + ((size_t)b*GS + i)*GS;
    float* orow = out + (size_t)b*OUTS + HALF + (size_t)i*GS;

    #pragma unroll 1
    for (int p = 0; p < 2; ++p){
        int jpA = p*64 + lane;
        int jpB = jpA + 32;
        int jpAc = min(jpA, 100), jpBc = min(jpB, 100);
        float yA0 = b3v, yA1 = b3v, yB0 = b3v, yB1 = b3v;
        #pragma unroll 1
        for (int hf = 0; hf < 2; ++hf){
            unsigned long long aA0[8], aA1[8], aB0[8], aB1[8];
            #pragma unroll
            for (int q = 0; q < 8; ++q){
                unsigned long long bb = b2p[hf*8 + q];
                aA0[q] = bb; aA1[q] = bb; aB0[q] = bb; aB1[q] = bb;
            }
            #pragma unroll 2
            for (int k = 0; k < 32; ++k){
                float2 vA = vp[k][jpAc];
                float2 vB = vp[k][jpBc];
                float uk = us[il][k];
                float hA0 = fmaxf(uk + vA.x, 0.f), hA1 = fmaxf(uk + vA.y, 0.f);
                float hB0 = fmaxf(uk + vB.x, 0.f), hB1 = fmaxf(uk + vB.y, 0.f);
                unsigned long long hA0d = pack2(hA0, hA0), hA1d = pack2(hA1, hA1);
                unsigned long long hB0d = pack2(hB0, hB0), hB1d = pack2(hB1, hB1);
                const ulonglong2* wrow = reinterpret_cast<const ulonglong2*>(&w2p[k][hf*8]);
                #pragma unroll
                for (int q = 0; q < 4; ++q){
                    ulonglong2 ww = wrow[q];
                    aA0[2*q]   = fma2(hA0d, ww.x, aA0[2*q]);
                    aA1[2*q]   = fma2(hA1d, ww.x, aA1[2*q]);
                    aB0[2*q]   = fma2(hB0d, ww.x, aB0[2*q]);
                    aB1[2*q]   = fma2(hB1d, ww.x, aB1[2*q]);
                    aA0[2*q+1] = fma2(hA0d, ww.y, aA0[2*q+1]);
                    aA1[2*q+1] = fma2(hA1d, ww.y, aA1[2*q+1]);
                    aB0[2*q+1] = fma2(hB0d, ww.y, aB0[2*q+1]);
                    aB1[2*q+1] = fma2(hB1d, ww.y, aB1[2*q+1]);
                }
            }
            #pragma unroll
            for (int q = 0; q < 8; ++q){
                float wa = w3s[hf*16 + 2*q], wb = w3s[hf*16 + 2*q + 1];
                float2 rA0 = unpack2(aA0[q]);
                yA0 = fmaf(fmaxf(rA0.x, 0.f), wa, yA0);
                yA0 = fmaf(fmaxf(rA0.y, 0.f), wb, yA0);
                float2 rA1 = unpack2(aA1[q]);
                yA1 = fmaf(fmaxf(rA1.x, 0.f), wa, yA1);
                yA1 = fmaf(fmaxf(rA1.y, 0.f), wb, yA1);
                float2 rB0 = unpack2(aB0[q]);
                yB0 = fmaf(fmaxf(rB0.x, 0.f), wa, yB0);
                yB0 = fmaf(fmaxf(rB0.y, 0.f), wb, yB0);
                float2 rB1 = unpack2(aB1[q]);
                yB1 = fmaf(fmaxf(rB1.x, 0.f), wa, yB1);
                yB1 = fmaf(fmaxf(rB1.y, 0.f), wb, yB1);
            }
        }
        {
            int j0 = 2*jpA, j1 = j0 + 1;
            if (iok && j0 < GS){
                float e = mrow[j0] ? 0.f : __expf(6.f * fast_tanh(yA0));
                orow[j0] = e; lsum += e;
                if (j1 < GS){
                    float e1 = mrow[j1] ? 0.f : __expf(6.f * fast_tanh(yA1));
                    orow[j1] = e1; lsum += e1;
                }
            }
        }
        {
            int j0 = 2*jpB, j1 = j0 + 1;
            if (iok && j0 < GS){
                float e = mrow[j0] ? 0.f : __expf(6.f * fast_tanh(yB0));
                orow[j0] = e; lsum += e;
                if (j1 < GS){
                    float e1 = mrow[j1] ? 0.f : __expf(6.f * fast_tanh(yB1));
                    orow[j1] = e1; lsum += e1;
                }
            }
        }
    }
    #pragma unroll
    for (int o = 16; o; o >>= 1) lsum += __shfl_xor_sync(0xffffffffu, lsum, o);
    if (lane == 0) red[il] = lsum;
    __syncthreads();
    if (tid == 0){
        float tot = 0.f;
        #pragma unroll
        for (int w = 0; w < 8; ++w) tot += red[w];
        g_part[b*NTILES + it] = tot;
    }
}

// ---- deterministic row sums -> reciprocal ----
__global__ void k_inv(){
    int b = blockIdx.x, t = threadIdx.x;
    float v = (t < NTILES) ? g_part[b*NTILES + t] : 0.f;
    #pragma unroll
    for (int o = 16; o; o >>= 1) v += __shfl_xor_sync(0xffffffffu, v, o);
    if (t == 0) g_sums[b] = __frcp_rn(v);
}

// ---- normalize reinsertion block ----
__global__ void k_scale(float* __restrict__ out){
    int idx = blockIdx.x*256 + threadIdx.x;
    if (idx >= BS*GS2) return;
    int b = idx / GS2;
    out[(size_t)b*OUTS + HALF + (idx - b*GS2)] *= g_sums[b];
}

extern "C" void kernel_launch(void* const* d_in, const int* in_sizes, int n_in,
                              void* d_out, int out_size) {
    const float* h_em  = (const float*)d_in[0];
    const float* sig   = (const float*)d_in[1];
    const float* Wn    = (const float*)d_in[2];
    const float* Wg    = (const float*)d_in[3];
    const float* WQr   = (const float*)d_in[4];
    const float* WKr   = (const float*)d_in[5];
    const float* r_w1  = (const float*)d_in[6];
    const float* r_b1  = (const float*)d_in[7];
    const float* r_w2  = (const float*)d_in[8];
    const float* r_b2  = (const float*)d_in[9];
    const float* r_w3  = (const float*)d_in[10];
    const float* r_b3  = (const float*)d_in[11];
    const float* Wq1   = (const float*)d_in[12];
    const float* Wk1   = (const float*)d_in[13];
    const float* Wq2   = (const float*)d_in[14];
    const float* Wk2   = (const float*)d_in[15];
    const float* i_w1  = (const float*)d_in[16];
    const float* i_b1  = (const float*)d_in[17];
    const float* i_w2  = (const float*)d_in[18];
    const float* i_b2  = (const float*)d_in[19];
    const float* i_w3  = (const float*)d_in[20];
    const float* i_b3  = (const float*)d_in[21];
    const int*   rec   = (const int*)d_in[22];
    const int*   fixed = (const int*)d_in[23];
    const unsigned char* mask = (const unsigned char*)d_in[24];
    float* out = (float*)d_out;

    k_pg<<<192, 256>>>(Wq1, Wk1, Wq2, Wk2, h_em, Wg);          // #1
    k_gemm0<<<402, 256>>>(h_em, Wn);                            // #2
    k_uvq<<<dim3(BS, 4), 256>>>(rec, fixed, i_w1, i_b1);        // #3
    k_gemmQK<<<dim3(402, 2), 256>>>(WQr, WKr);                  // #4 (ncu capture slot)
    k_table<<<dim3(NTILES, BS), 256>>>(i_w2, i_b2, i_w3, i_b3, mask, out);  // #5
    k_removal<<<BS, 128>>>(rec, sig, r_w1, r_b1, r_w2, r_b2, r_w3, r_b3, out);
    k_inv<<<BS, 32>>>();
    k_scale<<<(BS*GS2 + 255)/256, 256>>>(out);
}

// round 17
// speedup vs baseline: 1.0047x; 1.0047x over previous
#include <cuda_runtime.h>
#include <cuda_bf16.h>

#define BS 128
#define GS 201
#define DIM 128
#define HALF 100
#define GS2 (GS*GS)
#define OUTS (HALF + GS2)
#define NORMF 0.08838834764831845f
#define NTILES 26

// ---- device scratch ----
__device__ float g_gb[BS*DIM];
__device__ float g_h[BS*GS*DIM];
__device__ float g_hQ[BS*GS*DIM];
__device__ float g_hK[BS*GS*DIM];
__device__ float g_Mt[8*DIM*DIM];
__device__ float g_u[BS*GS*32];
__device__ float g_v[BS*GS*32];
__device__ float g_part[BS*NTILES];
__device__ float g_sums[BS];

// ---- f32x2 helpers ----
__device__ __forceinline__ unsigned long long pack2(float lo, float hi){
    unsigned long long r; asm("mov.b64 %0, {%1, %2};" : "=l"(r) : "f"(lo), "f"(hi)); return r;
}
__device__ __forceinline__ float2 unpack2(unsigned long long v){
    float2 r; asm("mov.b64 {%0, %1}, %2;" : "=f"(r.x), "=f"(r.y) : "l"(v)); return r;
}
__device__ __forceinline__ unsigned long long fma2(unsigned long long a, unsigned long long b, unsigned long long c){
    unsigned long long r; asm("fma.rn.f32x2 %0, %1, %2, %3;" : "=l"(r) : "l"(a), "l"(b), "l"(c)); return r;
}
__device__ __forceinline__ float fast_tanh(float y){
    y = fminf(fmaxf(y, -15.f), 15.f);
    float e = __expf(2.f*y);
    return __fdividef(e-1.f, e+1.f);
}

// ---- k_pg: fused k_prep (blocks 0..63) + k_gg (blocks 64..191) ----
__global__ __launch_bounds__(256) void k_pg(const float* __restrict__ Wq1, const float* __restrict__ Wk1,
                                            const float* __restrict__ Wq2, const float* __restrict__ Wk2,
                                            const float* __restrict__ h_em, const float* __restrict__ Wg){
    int blk = blockIdx.x;
    int tid = threadIdx.x;
    if (blk < 64){
        __shared__ float Wqs[16][33];
        __shared__ float Wks[32][129];
        int mat = blk >> 3, kt = blk & 7;
        int s = mat >> 2, h = mat & 3;
        const float* Wq = (s ? Wq2 : Wq1) + h*DIM*DIM;
        const float* Wk = (s ? Wk2 : Wk1) + h*DIM*DIM;
        int j = tid & 127, rr = tid >> 7;
        float acc[8];
        #pragma unroll
        for (int r = 0; r < 8; ++r) acc[r] = 0.f;
        for (int e0 = 0; e0 < DIM; e0 += 32){
            for (int idx = tid; idx < 16*32; idx += 256){
                int r = idx >> 5, e = idx & 31;
                Wqs[r][e] = Wq[(kt*16 + r)*DIM + e0 + e];
            }
            for (int idx = tid; idx < 128*32; idx += 256){
                int row = idx >> 5, e = idx & 31;
                Wks[e][row] = Wk[row*DIM + e0 + e];
            }
            __syncthreads();
            #pragma unroll 8
            for (int e = 0; e < 32; ++e){
                float wv = Wks[e][j];
                #pragma unroll
                for (int r = 0; r < 8; ++r)
                    acc[r] = fmaf(Wqs[rr*8 + r][e], wv, acc[r]);
            }
            __syncthreads();
        }
        #pragma unroll
        for (int r = 0; r < 8; ++r)
            g_Mt[mat*DIM*DIM + (kt*16 + rr*8 + r)*DIM + j] = acc[r];
    } else {
        __shared__ float xs[DIM];
        int b = blk - 64, d = tid;
        if (d < DIM){
            const float* p = h_em + (size_t)b*GS*DIM + d;
            float m = -1e30f;
            for (int g = 0; g < GS; ++g) m = fmaxf(m, p[(size_t)g*DIM]);
            xs[d] = m;
        }
        __syncthreads();
        if (d < DIM){
            float acc = 0.f;
            #pragma unroll 8
            for (int i = 0; i < DIM; ++i) acc = fmaf(xs[i], Wg[i*DIM+d], acc);
            g_gb[b*DIM+d] = acc;
        }
    }
}

// ---- GEMM mode 0 v3: h = h_em@Wn + gb, transposed A smem (LDS.128 A loads) ----
__global__ __launch_bounds__(256) void k_gemm0(const float* __restrict__ A, const float* __restrict__ B){
    __shared__ float As[16][68];      // [k][row], row-chunk 16B aligned
    __shared__ float Bs[16][128];
    int tid = threadIdx.x;
    int tx = tid & 15, ty = tid >> 4;
    int row0 = blockIdx.x * 64;
    float acc[4][8];
    #pragma unroll
    for (int a = 0; a < 4; ++a)
        #pragma unroll
        for (int c = 0; c < 8; ++c) acc[a][c] = 0.f;
    int la_r = tid >> 2, la_k = (tid & 3)*4;
    int lb_r = tid >> 4, lb_c = (tid & 15)*8;
    for (int kc = 0; kc < DIM; kc += 16){
        float4 av = *reinterpret_cast<const float4*>(A + (size_t)(row0+la_r)*DIM + kc + la_k);
        const float* bp = B + (kc+lb_r)*DIM + lb_c;
        float4 bv0 = *reinterpret_cast<const float4*>(bp);
        float4 bv1 = *reinterpret_cast<const float4*>(bp+4);
        As[la_k+0][la_r]=av.x; As[la_k+1][la_r]=av.y; As[la_k+2][la_r]=av.z; As[la_k+3][la_r]=av.w;
        *reinterpret_cast<float4*>(&Bs[lb_r][lb_c])   = bv0;
        *reinterpret_cast<float4*>(&Bs[lb_r][lb_c+4]) = bv1;
        __syncthreads();
        #pragma unroll
        for (int k = 0; k < 16; ++k){
            float4 a4 = *reinterpret_cast<const float4*>(&As[k][ty*4]);
            float4 b0 = *reinterpret_cast<const float4*>(&Bs[k][tx*8]);
            float4 b1 = *reinterpret_cast<const float4*>(&Bs[k][tx*8+4]);
            float bb[8] = {b0.x,b0.y,b0.z,b0.w,b1.x,b1.y,b1.z,b1.w};
            #pragma unroll
            for (int c = 0; c < 8; ++c){
                acc[0][c]=fmaf(a4.x,bb[c],acc[0][c]); acc[1][c]=fmaf(a4.y,bb[c],acc[1][c]);
                acc[2][c]=fmaf(a4.z,bb[c],acc[2][c]); acc[3][c]=fmaf(a4.w,bb[c],acc[3][c]);
            }
        }
        __syncthreads();
    }
    #pragma unroll
    for (int a = 0; a < 4; ++a){
        int row = row0 + ty*4 + a;
        #pragma unroll
        for (int c = 0; c < 8; ++c)
            g_h[(size_t)row*DIM + tx*8 + c] = acc[a][c] + g_gb[(row/GS)*DIM + tx*8 + c];
    }
}

// ---- k_uvq: fused qW (via Mt) + per-node layer-1 pre-activations. grid (BS, 4). ----
__global__ __launch_bounds__(256) void k_uvq(const int* __restrict__ rec, const int* __restrict__ fixed_action,
                                             const float* __restrict__ i_w1, const float* __restrict__ i_b1){
    __shared__ float xsel[2][DIM];
    __shared__ float qw[16*133];
    __shared__ float xg[8][DIM], xn[8][DIM];
    __shared__ float sfeat[8][16];
    __shared__ float w1s[16][32];
    __shared__ float b1s[32];
    __shared__ int recs[GS];
    int b = blockIdx.x, cq = blockIdx.y, tid = threadIdx.x;

    for (int idx = tid; idx < GS; idx += 256) recs[idx] = rec[b*GS + idx];
    for (int idx = tid; idx < 16*32; idx += 256) w1s[idx>>5][idx&31] = i_w1[idx];
    if (tid < 32) b1s[tid] = i_b1[tid];
    {
        int pos = 1 + fixed_action[b*3];
        int vs = tid >> 7, e = tid & 127;
        int row = vs ? pos + HALF : pos;
        xsel[vs][e] = g_h[((size_t)b*GS + row)*DIM + e];
    }
    __syncthreads();

    #pragma unroll
    for (int r = 0; r < 8; ++r){
        int idx = r*256 + tid;
        int vec = idx >> 7, t = idx & 127;
        int combo = vec >> 2, head = vec & 3;
        int mat = (combo & 1)*4 + head;
        const float* Mh = g_Mt + (size_t)mat*DIM*DIM;
        const float* x = xsel[(combo & 2) ? 1 : 0];
        float acc = 0.f;
        #pragma unroll 4
        for (int k = 0; k < DIM; ++k) acc = fmaf(x[k], Mh[k*DIM + t], acc);
        qw[vec*133 + t] = acc;
    }
    __syncthreads();

    int c_end = min(cq*7 + 7, 26);
    for (int c = cq*7; c < c_end; ++c){
        {
            int g_loc = tid >> 5, e4 = tid & 31;
            int g = c*8 + g_loc;
            int gc = min(g, GS-1);
            const float4* hg = reinterpret_cast<const float4*>(g_h + ((size_t)b*GS + gc)*DIM) + e4;
            const float4* hn = reinterpret_cast<const float4*>(g_h + ((size_t)b*GS + recs[gc])*DIM) + e4;
            *(reinterpret_cast<float4*>(&xg[g_loc][0]) + e4) = *hg;
            *(reinterpret_cast<float4*>(&xn[g_loc][0]) + e4) = *hn;
        }
        __syncthreads();
        {
            int dot_id = tid >> 1, half = tid & 1;
            int g_loc = dot_id >> 4, vec = dot_id & 15;
            int combo = vec >> 2;
            const float* x = (combo & 1) ? xn[g_loc] : xg[g_loc];
            const float* q = qw + vec*133;
            float p = 0.f;
            #pragma unroll 8
            for (int i2 = 0; i2 < 64; ++i2){
                int e = 2*i2 + half;
                p = fmaf(q[e], x[e], p);
            }
            p += __shfl_xor_sync(0xffffffffu, p, 1);
            if (half == 0) sfeat[g_loc][vec] = p * NORMF;
        }
        __syncthreads();
        #pragma unroll
        for (int r = 0; r < 2; ++r){
            int out = r*256 + tid;
            int g_loc = out >> 6, c32 = out & 63;
            int g = c*8 + g_loc;
            if (g < GS){
                if (c32 < 32){
                    float u = b1s[c32];
                    #pragma unroll
                    for (int f = 0; f < 8; ++f) u = fmaf(sfeat[g_loc][f], w1s[f][c32], u);
                    g_u[((size_t)b*GS + g)*32 + c32] = u;
                } else {
                    int cc = c32 - 32;
                    float v = 0.f;
                    #pragma unroll
                    for (int f = 0; f < 8; ++f) v = fmaf(sfeat[g_loc][8+f], w1s[8+f][cc], v);
                    g_v[((size_t)b*GS + g)*32 + cc] = v;
                }
            }
        }
        __syncthreads();
    }
}

// ---- GEMM QK v6: Q/K split by blockIdx.y, 64-row tile, f32x2, transposed A smem ----
__global__ __launch_bounds__(256, 3) void k_gemmQK(const float* __restrict__ BQ, const float* __restrict__ BK){
    __shared__ float As[16][68];      // [k][row]
    __shared__ float Bs[16][128];
    const float* A = g_h;
    const float* B = blockIdx.y ? BK : BQ;
    float* C = blockIdx.y ? g_hK : g_hQ;
    int tid = threadIdx.x;
    int tx = tid & 15, ty = tid >> 4;
    int row0 = blockIdx.x * 64;
    unsigned long long acc[4][4];
    #pragma unroll
    for (int a = 0; a < 4; ++a)
        #pragma unroll
        for (int c = 0; c < 4; ++c) acc[a][c] = 0ull;
    int la_r = tid >> 2, la_k = (tid & 3)*4;
    int lb_r = tid >> 4, lb_c = (tid & 15)*8;
    for (int kc = 0; kc < DIM; kc += 16){
        float4 av = *reinterpret_cast<const float4*>(A + (size_t)(row0+la_r)*DIM + kc + la_k);
        size_t boff = (size_t)(lb_c>>5)*4096 + (kc+lb_r)*32 + (lb_c&31);
        float4 bv0 = *reinterpret_cast<const float4*>(B + boff);
        float4 bv1 = *reinterpret_cast<const float4*>(B + boff + 4);
        As[la_k+0][la_r]=av.x; As[la_k+1][la_r]=av.y; As[la_k+2][la_r]=av.z; As[la_k+3][la_r]=av.w;
        *reinterpret_cast<float4*>(&Bs[lb_r][lb_c])   = bv0;
        *reinterpret_cast<float4*>(&Bs[lb_r][lb_c+4]) = bv1;
        __syncthreads();
        #pragma unroll
        for (int k = 0; k < 16; ++k){
            float4 a4 = *reinterpret_cast<const float4*>(&As[k][ty*4]);
            unsigned long long ad[4];
            ad[0] = pack2(a4.x, a4.x);
            ad[1] = pack2(a4.y, a4.y);
            ad[2] = pack2(a4.z, a4.z);
            ad[3] = pack2(a4.w, a4.w);
            const ulonglong2* bp2 = reinterpret_cast<const ulonglong2*>(&Bs[k][tx*8]);
            ulonglong2 b01 = bp2[0];
            ulonglong2 b23 = bp2[1];
            #pragma unroll
            for (int r = 0; r < 4; ++r){
                acc[r][0] = fma2(ad[r], b01.x, acc[r][0]);
                acc[r][1] = fma2(ad[r], b01.y, acc[r][1]);
                acc[r][2] = fma2(ad[r], b23.x, acc[r][2]);
                acc[r][3] = fma2(ad[r], b23.y, acc[r][3]);
            }
        }
        __syncthreads();
    }
    #pragma unroll
    for (int a = 0; a < 4; ++a){
        int row = row0 + ty*4 + a;
        float* crow = C + (size_t)row*DIM + tx*8;
        #pragma unroll
        for (int c = 0; c < 4; ++c){
            float2 r = unpack2(acc[a][c]);
            crow[2*c]   = r.x;
            crow[2*c+1] = r.y;
        }
    }
}

// ---- removal scores ----
__global__ void k_removal(const int* __restrict__ rec, const float* __restrict__ sig,
                          const float* __restrict__ w1, const float* __restrict__ b1,
                          const float* __restrict__ w2, const float* __restrict__ b2,
                          const float* __restrict__ w3, const float* __restrict__ b3,
                          float* __restrict__ out){
    int b = blockIdx.x, t = threadIdx.x;
    __shared__ int rec_s[GS], pre_s[GS];
    __shared__ float red[4];
    __shared__ float tot_s;
    for (int g = t; g < GS; g += 128) rec_s[g] = rec[b*GS+g];
    __syncthreads();
    for (int g = t; g < GS; g += 128) pre_s[rec_s[g]] = g;
    __syncthreads();
    float e = 0.f;
    if (t < HALF){
        float feat[12];
        #pragma unroll
        for (int hf = 0; hf < 2; ++hf){
            int g = 1 + hf*HALF + t;
            int pg = pre_s[g];
            int og = rec_s[rec_s[g]];
            const float* Qg = g_hQ + ((size_t)b*GS + g )*DIM;
            const float* Kg = g_hK + ((size_t)b*GS + g )*DIM;
            const float* Qp = g_hQ + ((size_t)b*GS + pg)*DIM;
            const float* Kp = g_hK + ((size_t)b*GS + og)*DIM;
            #pragma unroll
            for (int h = 0; h < 4; ++h){
                float c1=0.f, c2=0.f, c3=0.f;
                #pragma unroll
                for (int k = 0; k < 32; ++k){
                    float qp=Qp[h*32+k], kg=Kg[h*32+k], qg=Qg[h*32+k], kp=Kp[h*32+k];
                    c1 = fmaf(qp, kg, c1);
                    c2 = fmaf(qg, kp, c2);
                    c3 = fmaf(qp, kp, c3);
                }
                feat[hf*4+h] = c1 + c2 - c3;
            }
        }
        #pragma unroll
        for (int s4 = 0; s4 < 4; ++s4) feat[8+s4] = sig[b*4*HALF + s4*HALF + t];
        float x1[32];
        #pragma unroll
        for (int c = 0; c < 32; ++c){
            float a = b1[c];
            #pragma unroll
            for (int f = 0; f < 12; ++f) a = fmaf(feat[f], w1[f*32+c], a);
            x1[c] = fmaxf(a, 0.f);
        }
        float y = b3[0];
        #pragma unroll
        for (int o = 0; o < 32; ++o){
            float a = b2[o];
            #pragma unroll
            for (int k = 0; k < 32; ++k) a = fmaf(x1[k], w2[k*32+o], a);
            y = fmaf(fmaxf(a, 0.f), w3[o], y);
        }
        e = __expf(6.f * tanhf(y));
    }
    float w = e;
    #pragma unroll
    for (int o = 16; o; o >>= 1) w += __shfl_xor_sync(0xffffffffu, w, o);
    if ((t & 31) == 0) red[t>>5] = w;
    __syncthreads();
    if (t == 0) tot_s = red[0]+red[1]+red[2]+red[3];
    __syncthreads();
    if (t < HALF) out[(size_t)b*OUTS + t] = e / tot_s;
}

// ---- table MLP v8 (unchanged, best): o-packed accs + 4-j amortization + coalesced vp ----
__global__ __launch_bounds__(256, 2) void k_table(
        const float* __restrict__ i_w2, const float* __restrict__ i_b2,
        const float* __restrict__ i_w3, const float* __restrict__ i_b3,
        const unsigned char* __restrict__ mask, float* __restrict__ out){
    __shared__ unsigned long long w2p[32][16];
    __shared__ float2 vp[32][101];
    __shared__ float us[8][32];
    __shared__ unsigned long long b2p[16];
    __shared__ float w3s[32];
    __shared__ float red[8];
    int tid = threadIdx.x, b = blockIdx.y, it = blockIdx.x;
    int lane = tid & 31, il = tid >> 5;

    const unsigned long long* w2u = reinterpret_cast<const unsigned long long*>(i_w2);
    #pragma unroll
    for (int r = 0; r < 2; ++r){
        int idx = r*256 + tid;
        w2p[idx >> 4][idx & 15] = w2u[idx];
    }
    if (tid < 16) b2p[tid] = reinterpret_cast<const unsigned long long*>(i_b2)[tid];
    if (tid < 32) w3s[tid] = i_w3[tid];
    const float* vbase = g_v + (size_t)b*GS*32;
    for (int j = il; j < GS; j += 8){
        float val = vbase[(size_t)j*32 + lane];
        reinterpret_cast<float*>(&vp[lane][j >> 1])[j & 1] = val;
    }
    if (il == 0) vp[lane][100].y = vbase[(size_t)200*32 + lane];
    {
        int i = it*8 + il;
        us[il][lane] = (i < GS) ? g_u[((size_t)b*GS + i)*32 + lane] : 0.f;
    }
    __syncthreads();

    int i = it*8 + il;
    bool iok = (i < GS);
    float b3v = i_b3[0];
    float lsum = 0.f;
    const unsigned char* mrow = mask + ((size_t)b*GS + i)*GS;
    float* orow = out + (size_t)b*OUTS + HALF + (size_t)i*GS;

    #pragma unroll 1
    for (int p = 0; p < 2; ++p){
        int jpA = p*64 + lane;
        int jpB = jpA + 32;
        int jpAc = min(jpA, 100), jpBc = min(jpB, 100);
        float yA0 = b3v, yA1 = b3v, yB0 = b3v, yB1 = b3v;
        #pragma unroll 1
        for (int hf = 0; hf < 2; ++hf){
            unsigned long long aA0[8], aA1[8], aB0[8], aB1[8];
            #pragma unroll
            for (int q = 0; q < 8; ++q){
                unsigned long long bb = b2p[hf*8 + q];
                aA0[q] = bb; aA1[q] = bb; aB0[q] = bb; aB1[q] = bb;
            }
            #pragma unroll 2
            for (int k = 0; k < 32; ++k){
                float2 vA = vp[k][jpAc];
                float2 vB = vp[k][jpBc];
                float uk = us[il][k];
                float hA0 = fmaxf(uk + vA.x, 0.f), hA1 = fmaxf(uk + vA.y, 0.f);
                float hB0 = fmaxf(uk + vB.x, 0.f), hB1 = fmaxf(uk + vB.y, 0.f);
                unsigned long long hA0d = pack2(hA0, hA0), hA1d = pack2(hA1, hA1);
                unsigned long long hB0d = pack2(hB0, hB0), hB1d = pack2(hB1, hB1);
                const ulonglong2* wrow = reinterpret_cast<const ulonglong2*>(&w2p[k][hf*8]);
                #pragma unroll
                for (int q = 0; q < 4; ++q){
                    ulonglong2 ww = wrow[q];
                    aA0[2*q]   = fma2(hA0d, ww.x, aA0[2*q]);
                    aA1[2*q]   = fma2(hA1d, ww.x, aA1[2*q]);
                    aB0[2*q]   = fma2(hB0d, ww.x, aB0[2*q]);
                    aB1[2*q]   = fma2(hB1d, ww.x, aB1[2*q]);
                    aA0[2*q+1] = fma2(hA0d, ww.y, aA0[2*q+1]);
                    aA1[2*q+1] = fma2(hA1d, ww.y, aA1[2*q+1]);
                    aB0[2*q+1] = fma2(hB0d, ww.y, aB0[2*q+1]);
                    aB1[2*q+1] = fma2(hB1d, ww.y, aB1[2*q+1]);
                }
            }
            #pragma unroll
            for (int q = 0; q < 8; ++q){
                float wa = w3s[hf*16 + 2*q], wb = w3s[hf*16 + 2*q + 1];
                float2 rA0 = unpack2(aA0[q]);
                yA0 = fmaf(fmaxf(rA0.x, 0.f), wa, yA0);
                yA0 = fmaf(fmaxf(rA0.y, 0.f), wb, yA0);
                float2 rA1 = unpack2(aA1[q]);
                yA1 = fmaf(fmaxf(rA1.x, 0.f), wa, yA1);
                yA1 = fmaf(fmaxf(rA1.y, 0.f), wb, yA1);
                float2 rB0 = unpack2(aB0[q]);
                yB0 = fmaf(fmaxf(rB0.x, 0.f), wa, yB0);
                yB0 = fmaf(fmaxf(rB0.y, 0.f), wb, yB0);
                float2 rB1 = unpack2(aB1[q]);
                yB1 = fmaf(fmaxf(rB1.x, 0.f), wa, yB1);
                yB1 = fmaf(fmaxf(rB1.y, 0.f), wb, yB1);
            }
        }
        {
            int j0 = 2*jpA, j1 = j0 + 1;
            if (iok && j0 < GS){
                float e = mrow[j0] ? 0.f : __expf(6.f * fast_tanh(yA0));
                orow[j0] = e; lsum += e;
                if (j1 < GS){
                    float e1 = mrow[j1] ? 0.f : __expf(6.f * fast_tanh(yA1));
                    orow[j1] = e1; lsum += e1;
                }
            }
        }
        {
            int j0 = 2*jpB, j1 = j0 + 1;
            if (iok && j0 < GS){
                float e = mrow[j0] ? 0.f : __expf(6.f * fast_tanh(yB0));
                orow[j0] = e; lsum += e;
                if (j1 < GS){
                    float e1 = mrow[j1] ? 0.f : __expf(6.f * fast_tanh(yB1));
                    orow[j1] = e1; lsum += e1;
                }
            }
        }
    }
    #pragma unroll
    for (int o = 16; o; o >>= 1) lsum += __shfl_xor_sync(0xffffffffu, lsum, o);
    if (lane == 0) red[il] = lsum;
    __syncthreads();
    if (tid == 0){
        float tot = 0.f;
        #pragma unroll
        for (int w = 0; w < 8; ++w) tot += red[w];
        g_part[b*NTILES + it] = tot;
    }
}

// ---- deterministic row sums -> reciprocal ----
__global__ void k_inv(){
    int b = blockIdx.x, t = threadIdx.x;
    float v = (t < NTILES) ? g_part[b*NTILES + t] : 0.f;
    #pragma unroll
    for (int o = 16; o; o >>= 1) v += __shfl_xor_sync(0xffffffffu, v, o);
    if (t == 0) g_sums[b] = __frcp_rn(v);
}

// ---- normalize reinsertion block ----
__global__ void k_scale(float* __restrict__ out){
    int idx = blockIdx.x*256 + threadIdx.x;
    if (idx >= BS*GS2) return;
    int b = idx / GS2;
    out[(size_t)b*OUTS + HALF + (idx - b*GS2)] *= g_sums[b];
}

extern "C" void kernel_launch(void* const* d_in, const int* in_sizes, int n_in,
                              void* d_out, int out_size) {
    const float* h_em  = (const float*)d_in[0];
    const float* sig   = (const float*)d_in[1];
    const float* Wn    = (const float*)d_in[2];
    const float* Wg    = (const float*)d_in[3];
    const float* WQr   = (const float*)d_in[4];
    const float* WKr   = (const float*)d_in[5];
    const float* r_w1  = (const float*)d_in[6];
    const float* r_b1  = (const float*)d_in[7];
    const float* r_w2  = (const float*)d_in[8];
    const float* r_b2  = (const float*)d_in[9];
    const float* r_w3  = (const float*)d_in[10];
    const float* r_b3  = (const float*)d_in[11];
    const float* Wq1   = (const float*)d_in[12];
    const float* Wk1   = (const float*)d_in[13];
    const float* Wq2   = (const float*)d_in[14];
    const float* Wk2   = (const float*)d_in[15];
    const float* i_w1  = (const float*)d_in[16];
    const float* i_b1  = (const float*)d_in[17];
    const float* i_w2  = (const float*)d_in[18];
    const float* i_b2  = (const float*)d_in[19];
    const float* i_w3  = (const float*)d_in[20];
    const float* i_b3  = (const float*)d_in[21];
    const int*   rec   = (const int*)d_in[22];
    const int*   fixed = (const int*)d_in[23];
    const unsigned char* mask = (const unsigned char*)d_in[24];
    float* out = (float*)d_out;

    k_pg<<<192, 256>>>(Wq1, Wk1, Wq2, Wk2, h_em, Wg);          // #1
    k_gemm0<<<402, 256>>>(h_em, Wn);                            // #2
    k_uvq<<<dim3(BS, 4), 256>>>(rec, fixed, i_w1, i_b1);        // #3
    k_gemmQK<<<dim3(402, 2), 256>>>(WQr, WKr);                  // #4 (ncu capture slot)
    k_table<<<dim3(NTILES, BS), 256>>>(i_w2, i_b2, i_w3, i_b3, mask, out);  // #5
    k_removal<<<BS, 128>>>(rec, sig, r_w1, r_b1, r_w2, r_b2, r_w3, r_b3, out);
    k_inv<<<BS, 32>>>();
    k_scale<<<(BS*GS2 + 255)/256, 256>>>(out);
}